// round 1
// baseline (speedup 1.0000x reference)
#include <cuda_runtime.h>

#define Bc 4
#define Cc 256
#define Nn 4096
#define DQv 32

// Scratch (device globals: no allocations allowed)
__device__ float g_Q[Bc*Nn*DQv];   // [b][n][32]
__device__ float g_K[Bc*Nn*DQv];   // [b][n][32]
__device__ float g_V[Bc*Nn*Cc];    // [b][n][256]

// ---------------------------------------------------------------------------
// Kernel 1: fused projection GEMM. Out[320, N] = W[320,256] @ x[256, N] + bias
// rows 0..31 -> Q, 32..63 -> K, 64..319 -> V. grid (N/128, 320/64, B), 256 thr.
// ---------------------------------------------------------------------------
__global__ void proj_kernel(const float* __restrict__ x,
                            const float* __restrict__ Wq, const float* __restrict__ bq,
                            const float* __restrict__ Wk, const float* __restrict__ bk,
                            const float* __restrict__ Wv, const float* __restrict__ bv)
{
    __shared__ float Ws[64*32];
    __shared__ float Xs[32*128];
    const int t  = threadIdx.x;
    const int n0 = blockIdx.x * 128;
    const int o0 = blockIdx.y * 64;
    const int b  = blockIdx.z;
    const int tr = t >> 5;        // warp id 0..7 -> rows tr*8..tr*8+7
    const int tc = t & 31;        // n cols tc*4..tc*4+3

    unsigned long long acc[8][2];
    #pragma unroll
    for (int r = 0; r < 8; r++) { acc[r][0] = 0ull; acc[r][1] = 0ull; }

    for (int k0 = 0; k0 < 256; k0 += 32) {
        __syncthreads();
        // load W tile [64 rows x 32 cols]
        #pragma unroll
        for (int it = 0; it < 2; it++) {
            int f = t + it*256;                 // float4 index 0..511
            int oo = f >> 3, c4 = f & 7;
            int o = o0 + oo;
            const float* src;
            if (o < 32)      src = Wq + o*256;
            else if (o < 64) src = Wk + (o-32)*256;
            else             src = Wv + (o-64)*256;
            float4 v = *(const float4*)(src + k0 + c4*4);
            *(float4*)(Ws + oo*32 + c4*4) = v;
        }
        // load X tile [32 c x 128 n]
        #pragma unroll
        for (int it = 0; it < 4; it++) {
            int f = t + it*256;                 // float4 index 0..1023
            int cc = f >> 5, n4 = f & 31;
            float4 v = *(const float4*)(x + ((size_t)b*Cc + k0 + cc)*Nn + n0 + n4*4);
            *(float4*)(Xs + cc*128 + n4*4) = v;
        }
        __syncthreads();
        #pragma unroll 4
        for (int cc = 0; cc < 32; cc++) {
            float4 xv = *(const float4*)(Xs + cc*128 + tc*4);
            unsigned long long x0, x1;
            asm("mov.b64 %0, {%1,%2};" : "=l"(x0) : "f"(xv.x), "f"(xv.y));
            asm("mov.b64 %0, {%1,%2};" : "=l"(x1) : "f"(xv.z), "f"(xv.w));
            #pragma unroll
            for (int r = 0; r < 8; r++) {
                float w = Ws[(tr*8 + r)*32 + cc];   // all-lane broadcast
                unsigned long long w2;
                asm("mov.b64 %0, {%1,%1};" : "=l"(w2) : "f"(w));
                asm("fma.rn.f32x2 %0, %1, %2, %0;" : "+l"(acc[r][0]) : "l"(x0), "l"(w2));
                asm("fma.rn.f32x2 %0, %1, %2, %0;" : "+l"(acc[r][1]) : "l"(x1), "l"(w2));
            }
        }
    }
    // write with bias; Q/K as [b][n][32], V as [b][n][256]
    #pragma unroll
    for (int r = 0; r < 8; r++) {
        int o = o0 + tr*8 + r;
        float bsv; float* dst; int stride; int od;
        if (o < 32)      { bsv = bq[o];    dst = g_Q; stride = DQv; od = o; }
        else if (o < 64) { bsv = bk[o-32]; dst = g_K; stride = DQv; od = o-32; }
        else             { bsv = bv[o-64]; dst = g_V; stride = Cc;  od = o-64; }
        float f0,f1,f2,f3;
        asm("mov.b64 {%0,%1}, %2;" : "=f"(f0), "=f"(f1) : "l"(acc[r][0]));
        asm("mov.b64 {%0,%1}, %2;" : "=f"(f2), "=f"(f3) : "l"(acc[r][1]));
        int nb = n0 + tc*4;
        dst[((size_t)b*Nn + nb+0)*stride + od] = f0 + bsv;
        dst[((size_t)b*Nn + nb+1)*stride + od] = f1 + bsv;
        dst[((size_t)b*Nn + nb+2)*stride + od] = f2 + bsv;
        dst[((size_t)b*Nn + nb+3)*stride + od] = f3 + bsv;
    }
}

// ---------------------------------------------------------------------------
// Kernel 2: flash attention + residual. grid (N/64, B), 256 threads.
//  Per key tile (64): S stage (si=t>>2 row, scg=t&3 -> 16 j's each) computes
//  scores + online softmax into Ps; PV stage (ti=t>>4 -> 4 rows, tc=t&15 ->
//  16 c's) accumulates O with fma.rn.f32x2.
// ---------------------------------------------------------------------------
#define PS_W 68
#define VS_W 260
#define OS_W 258
#define SMEM_FLOATS (64*36 + 64*36 + 64*PS_W + 64*VS_W + 64 + 64)

__global__ void attn_kernel(const float* __restrict__ x, float* __restrict__ out)
{
    extern __shared__ float sm[];
    float* Qs  = sm;                 // 64 x 36
    float* Ks  = sm + 64*36;         // 64 x 36
    float* Ps  = sm + 2*64*36;       // 64 x 68
    float* Vs  = Ps + 64*PS_W;       // 64 x 260  (reused as Os, stride 258)
    float* scs = Vs + 64*VS_W;       // 64
    float* ls  = scs + 64;           // 64

    const int t  = threadIdx.x;
    const int b  = blockIdx.y;
    const int i0 = blockIdx.x * 64;

    // load Q tile [64][32]
    #pragma unroll
    for (int it = 0; it < 2; it++) {
        int f = t + it*256;
        int row = f >> 3, d4 = f & 7;
        float4 v = *(const float4*)(g_Q + ((size_t)b*Nn + i0 + row)*DQv + d4*4);
        *(float4*)(Qs + row*36 + d4*4) = v;
    }

    const int si  = t >> 2;          // S-role: row 0..63
    const int scg = t & 3;           // S-role: j-group
    const int ti  = t >> 4;          // PV-role: rows ti*4 + r
    const int tc  = t & 15;          // PV-role: c = tc*16 + q

    float m_i = -1e30f, l_i = 0.f;
    unsigned long long acc[32];      // 4 rows x 16 c (8 f32x2 each)
    #pragma unroll
    for (int k = 0; k < 32; k++) acc[k] = 0ull;

    for (int jt = 0; jt < 64; jt++) {
        const int j0 = jt * 64;
        __syncthreads();             // prior PV done with Ps/Vs
        // load K tile [64][32]
        #pragma unroll
        for (int it = 0; it < 2; it++) {
            int f = t + it*256;
            int row = f >> 3, d4 = f & 7;
            float4 v = *(const float4*)(g_K + ((size_t)b*Nn + j0 + row)*DQv + d4*4);
            *(float4*)(Ks + row*36 + d4*4) = v;
        }
        // load V tile [64][256]
        #pragma unroll
        for (int it = 0; it < 16; it++) {
            int f = t + it*256;
            int row = f >> 6, c4 = f & 63;
            float4 v = *(const float4*)(g_V + ((size_t)b*Nn + j0 + row)*Cc + c4*4);
            *(float4*)(Vs + row*VS_W + c4*4) = v;
        }
        __syncthreads();

        // ---- S stage + online softmax ----
        float s[16];
        const float4* q4 = (const float4*)(Qs + si*36);
        #pragma unroll
        for (int idx = 0; idx < 16; idx++) {
            int jj = scg + idx*4;
            const float4* k4 = (const float4*)(Ks + jj*36);
            float a0 = 0.f, a1 = 0.f, a2 = 0.f, a3 = 0.f;
            #pragma unroll
            for (int d = 0; d < 8; d++) {
                float4 qv = q4[d], kv = k4[d];
                a0 = fmaf(qv.x, kv.x, a0);
                a1 = fmaf(qv.y, kv.y, a1);
                a2 = fmaf(qv.z, kv.z, a2);
                a3 = fmaf(qv.w, kv.w, a3);
            }
            s[idx] = (a0 + a1) + (a2 + a3);
        }
        float tmax = s[0];
        #pragma unroll
        for (int idx = 1; idx < 16; idx++) tmax = fmaxf(tmax, s[idx]);
        tmax = fmaxf(tmax, __shfl_xor_sync(0xffffffffu, tmax, 1));
        tmax = fmaxf(tmax, __shfl_xor_sync(0xffffffffu, tmax, 2));
        float m_new = fmaxf(m_i, tmax);
        float scale = __expf(m_i - m_new);
        float psum = 0.f;
        #pragma unroll
        for (int idx = 0; idx < 16; idx++) {
            float p = __expf(s[idx] - m_new);
            Ps[si*PS_W + scg + idx*4] = p;
            psum += p;
        }
        psum += __shfl_xor_sync(0xffffffffu, psum, 1);
        psum += __shfl_xor_sync(0xffffffffu, psum, 2);
        l_i = l_i * scale + psum;
        m_i = m_new;
        if (scg == 0) scs[si] = scale;
        __syncthreads();

        // ---- PV stage ----
        #pragma unroll
        for (int r = 0; r < 4; r++) {
            float sv = scs[ti*4 + r];
            unsigned long long s2;
            asm("mov.b64 %0, {%1,%1};" : "=l"(s2) : "f"(sv));
            #pragma unroll
            for (int kk = 0; kk < 8; kk++)
                asm("mul.rn.f32x2 %0, %0, %1;" : "+l"(acc[r*8+kk]) : "l"(s2));
        }
        #pragma unroll 2
        for (int j = 0; j < 64; j++) {
            unsigned long long p2[4];
            #pragma unroll
            for (int r = 0; r < 4; r++) {
                float pv = Ps[(ti*4 + r)*PS_W + j];    // all-lane broadcast
                asm("mov.b64 %0, {%1,%1};" : "=l"(p2[r]) : "f"(pv));
            }
            const ulonglong2* vp = (const ulonglong2*)(Vs + j*VS_W + tc*16);
            ulonglong2 va = vp[0], vb = vp[1], vc = vp[2], vd = vp[3];
            unsigned long long vv[8] = {va.x, va.y, vb.x, vb.y, vc.x, vc.y, vd.x, vd.y};
            #pragma unroll
            for (int r = 0; r < 4; r++) {
                #pragma unroll
                for (int kk = 0; kk < 8; kk++)
                    asm("fma.rn.f32x2 %0, %1, %2, %0;"
                        : "+l"(acc[r*8+kk]) : "l"(vv[kk]), "l"(p2[r]));
            }
        }
    }

    if (scg == 0) ls[si] = l_i;
    __syncthreads();                 // also: everyone done reading Vs

    // normalize and stage O into smem (stride 258, 8B-aligned ull stores)
    float* Os = Vs;
    #pragma unroll
    for (int r = 0; r < 4; r++) {
        int ir = ti*4 + r;
        float inv = 1.0f / ls[ir];
        unsigned long long inv2;
        asm("mov.b64 %0, {%1,%1};" : "=l"(inv2) : "f"(inv));
        unsigned long long* od = (unsigned long long*)(Os + ir*OS_W + tc*16);
        #pragma unroll
        for (int kk = 0; kk < 8; kk++) {
            unsigned long long v;
            asm("mul.rn.f32x2 %0, %1, %2;" : "=l"(v) : "l"(acc[r*8+kk]), "l"(inv2));
            od[kk] = v;
        }
    }
    __syncthreads();

    // coalesced output + residual: out[b][c][i0+n] = x + Os[n][c]
    const int chi = t >> 6;          // 0..3
    const int n   = t & 63;
    const float* xb = x   + (size_t)b*Cc*Nn;
    float*       ob = out + (size_t)b*Cc*Nn;
    #pragma unroll 4
    for (int ccc = 0; ccc < 64; ccc++) {
        int c = chi*64 + ccc;
        size_t g = (size_t)c*Nn + i0 + n;
        ob[g] = xb[g] + Os[n*OS_W + c];
    }
}

// ---------------------------------------------------------------------------
extern "C" void kernel_launch(void* const* d_in, const int* in_sizes, int n_in,
                              void* d_out, int out_size)
{
    const float* x  = (const float*)d_in[0];
    const float* Wq = (const float*)d_in[1];
    const float* bq = (const float*)d_in[2];
    const float* Wk = (const float*)d_in[3];
    const float* bk = (const float*)d_in[4];
    const float* Wv = (const float*)d_in[5];
    const float* bv = (const float*)d_in[6];
    float* out = (float*)d_out;

    const int smem_bytes = SMEM_FLOATS * 4;   // 102912 B
    cudaFuncSetAttribute(attn_kernel, cudaFuncAttributeMaxDynamicSharedMemorySize,
                         smem_bytes);

    proj_kernel<<<dim3(Nn/128, 320/64, Bc), 256>>>(x, Wq, bq, Wk, bk, Wv, bv);
    attn_kernel<<<dim3(Nn/64, Bc), 256, smem_bytes>>>(x, out);
}

// round 2
// speedup vs baseline: 2.3693x; 2.3693x over previous
#include <cuda_runtime.h>

#define Bc 4
#define Cc 256
#define Nn 4096
#define DQv 32

// Scratch (device globals: no allocations allowed)
__device__ float g_Q[Bc*Nn*DQv];   // [b][n][32]
__device__ float g_K[Bc*Nn*DQv];   // [b][n][32]
__device__ float g_V[Bc*Nn*Cc];    // [b][n][256]

// ---------------------------------------------------------------------------
// Kernel 1: fused projection GEMM. Out[320, N] = W[320,256] @ x[256, N] + bias
// ---------------------------------------------------------------------------
__global__ void proj_kernel(const float* __restrict__ x,
                            const float* __restrict__ Wq, const float* __restrict__ bq,
                            const float* __restrict__ Wk, const float* __restrict__ bk,
                            const float* __restrict__ Wv, const float* __restrict__ bv)
{
    __shared__ float Ws[64*32];
    __shared__ float Xs[32*128];
    const int t  = threadIdx.x;
    const int n0 = blockIdx.x * 128;
    const int o0 = blockIdx.y * 64;
    const int b  = blockIdx.z;
    const int tr = t >> 5;
    const int tc = t & 31;

    unsigned long long acc[8][2];
    #pragma unroll
    for (int r = 0; r < 8; r++) { acc[r][0] = 0ull; acc[r][1] = 0ull; }

    for (int k0 = 0; k0 < 256; k0 += 32) {
        __syncthreads();
        #pragma unroll
        for (int it = 0; it < 2; it++) {
            int f = t + it*256;
            int oo = f >> 3, c4 = f & 7;
            int o = o0 + oo;
            const float* src;
            if (o < 32)      src = Wq + o*256;
            else if (o < 64) src = Wk + (o-32)*256;
            else             src = Wv + (o-64)*256;
            float4 v = *(const float4*)(src + k0 + c4*4);
            *(float4*)(Ws + oo*32 + c4*4) = v;
        }
        #pragma unroll
        for (int it = 0; it < 4; it++) {
            int f = t + it*256;
            int cc = f >> 5, n4 = f & 31;
            float4 v = *(const float4*)(x + ((size_t)b*Cc + k0 + cc)*Nn + n0 + n4*4);
            *(float4*)(Xs + cc*128 + n4*4) = v;
        }
        __syncthreads();
        #pragma unroll 4
        for (int cc = 0; cc < 32; cc++) {
            float4 xv = *(const float4*)(Xs + cc*128 + tc*4);
            unsigned long long x0, x1;
            asm("mov.b64 %0, {%1,%2};" : "=l"(x0) : "f"(xv.x), "f"(xv.y));
            asm("mov.b64 %0, {%1,%2};" : "=l"(x1) : "f"(xv.z), "f"(xv.w));
            #pragma unroll
            for (int r = 0; r < 8; r++) {
                float w = Ws[(tr*8 + r)*32 + cc];
                unsigned long long w2;
                asm("mov.b64 %0, {%1,%1};" : "=l"(w2) : "f"(w));
                asm("fma.rn.f32x2 %0, %1, %2, %0;" : "+l"(acc[r][0]) : "l"(x0), "l"(w2));
                asm("fma.rn.f32x2 %0, %1, %2, %0;" : "+l"(acc[r][1]) : "l"(x1), "l"(w2));
            }
        }
    }
    #pragma unroll
    for (int r = 0; r < 8; r++) {
        int o = o0 + tr*8 + r;
        float bsv; float* dst; int stride; int od;
        if (o < 32)      { bsv = bq[o];    dst = g_Q; stride = DQv; od = o; }
        else if (o < 64) { bsv = bk[o-32]; dst = g_K; stride = DQv; od = o-32; }
        else             { bsv = bv[o-64]; dst = g_V; stride = Cc;  od = o-64; }
        float f0,f1,f2,f3;
        asm("mov.b64 {%0,%1}, %2;" : "=f"(f0), "=f"(f1) : "l"(acc[r][0]));
        asm("mov.b64 {%0,%1}, %2;" : "=f"(f2), "=f"(f3) : "l"(acc[r][1]));
        int nb = n0 + tc*4;
        dst[((size_t)b*Nn + nb+0)*stride + od] = f0 + bsv;
        dst[((size_t)b*Nn + nb+1)*stride + od] = f1 + bsv;
        dst[((size_t)b*Nn + nb+2)*stride + od] = f2 + bsv;
        dst[((size_t)b*Nn + nb+3)*stride + od] = f3 + bsv;
    }
}

// ---------------------------------------------------------------------------
// Kernel 2: flash attention + residual. grid (N/64, B), 256 threads.
// S stage: thread = (4 query rows, 4 keys) reading transposed Qs[d][row],
//          Ks[d][j]; f32x2 FMAs paired over j.
// PV stage: warp rg owns 8 rows; lane cg owns cols {cg*4..+3, 128+cg*4..+3};
//           P read transposed Ps[j][row] via broadcast float4.
// ---------------------------------------------------------------------------
#define QS_W 68
#define PS_W 68
#define VS_W 260
#define SMEM_FLOATS (2*32*QS_W + 64*PS_W + 64*VS_W + 64 + 64)

__global__ void __launch_bounds__(256, 1)
attn_kernel(const float* __restrict__ x, float* __restrict__ out)
{
    extern __shared__ float sm[];
    float* Qs  = sm;                    // 32 x 68  (transposed: [d][row])
    float* Ks  = Qs + 32*QS_W;          // 32 x 68  (transposed: [d][j])
    float* Ps  = Ks + 32*QS_W;          // 64 x 68  (transposed: [j][row])
    float* Vs  = Ps + 64*PS_W;          // 64 x 260 ([j][c]); reused as Os
    float* scs = Vs + 64*VS_W;          // 64
    float* ls  = scs + 64;              // 64

    const int t  = threadIdx.x;
    const int b  = blockIdx.y;
    const int i0 = blockIdx.x * 64;

    // stage Q transposed: Qs[d][row]
    #pragma unroll
    for (int it = 0; it < 2; it++) {
        int f = t + it*256;
        int row = f >> 3, d4 = f & 7;
        float4 v = *(const float4*)(g_Q + ((size_t)b*Nn + i0 + row)*DQv + d4*4);
        Qs[(d4*4+0)*QS_W + row] = v.x;
        Qs[(d4*4+1)*QS_W + row] = v.y;
        Qs[(d4*4+2)*QS_W + row] = v.z;
        Qs[(d4*4+3)*QS_W + row] = v.w;
    }

    const int ri = t >> 4;              // S-role: rows ri*4+r
    const int jc = t & 15;              // S-role: keys jc*4+jj
    const int rg = t >> 5;              // PV-role: warp -> rows rg*8+r
    const int cg = t & 31;              // PV-role: cols cg*4, 128+cg*4

    float m_i[4], l_i[4];
    #pragma unroll
    for (int r = 0; r < 4; r++) { m_i[r] = -1e30f; l_i[r] = 0.f; }

    unsigned long long acc[32];         // [r][k]: 8 rows x 4 f32x2 pairs
    #pragma unroll
    for (int k = 0; k < 32; k++) acc[k] = 0ull;

    for (int jt = 0; jt < 64; jt++) {
        const int j0 = jt * 64;
        __syncthreads();                // prior PV done with Ps/Vs

        // stage K transposed: Ks[d][j]
        #pragma unroll
        for (int it = 0; it < 2; it++) {
            int f = t + it*256;
            int row = f >> 3, d4 = f & 7;
            float4 v = *(const float4*)(g_K + ((size_t)b*Nn + j0 + row)*DQv + d4*4);
            Ks[(d4*4+0)*QS_W + row] = v.x;
            Ks[(d4*4+1)*QS_W + row] = v.y;
            Ks[(d4*4+2)*QS_W + row] = v.z;
            Ks[(d4*4+3)*QS_W + row] = v.w;
        }
        // stage V: Vs[j][c]
        #pragma unroll
        for (int it = 0; it < 16; it++) {
            int f = t + it*256;
            int row = f >> 6, c4 = f & 63;
            float4 v = *(const float4*)(g_V + ((size_t)b*Nn + j0 + row)*Cc + c4*4);
            *(float4*)(Vs + row*VS_W + c4*4) = v;
        }
        __syncthreads();

        // ---- S stage: 4 rows x 4 j per thread, f32x2 paired over j ----
        unsigned long long sacc[4][2];
        #pragma unroll
        for (int r = 0; r < 4; r++) { sacc[r][0] = 0ull; sacc[r][1] = 0ull; }

        #pragma unroll 8
        for (int d = 0; d < 32; d++) {
            float4 qv = *(const float4*)(Qs + d*QS_W + ri*4);
            float4 kv = *(const float4*)(Ks + d*QS_W + jc*4);
            unsigned long long k01, k23;
            asm("mov.b64 %0, {%1,%2};" : "=l"(k01) : "f"(kv.x), "f"(kv.y));
            asm("mov.b64 %0, {%1,%2};" : "=l"(k23) : "f"(kv.z), "f"(kv.w));
            const float* qa = (const float*)&qv;
            #pragma unroll
            for (int r = 0; r < 4; r++) {
                unsigned long long q2;
                asm("mov.b64 %0, {%1,%1};" : "=l"(q2) : "f"(qa[r]));
                asm("fma.rn.f32x2 %0, %1, %2, %0;" : "+l"(sacc[r][0]) : "l"(q2), "l"(k01));
                asm("fma.rn.f32x2 %0, %1, %2, %0;" : "+l"(sacc[r][1]) : "l"(q2), "l"(k23));
            }
        }

        // ---- online softmax (rows shared by 16 lanes of a half-warp) ----
        #pragma unroll
        for (int r = 0; r < 4; r++) {
            float s0,s1,s2,s3;
            asm("mov.b64 {%0,%1}, %2;" : "=f"(s0), "=f"(s1) : "l"(sacc[r][0]));
            asm("mov.b64 {%0,%1}, %2;" : "=f"(s2), "=f"(s3) : "l"(sacc[r][1]));
            float tmax = fmaxf(fmaxf(s0,s1), fmaxf(s2,s3));
            tmax = fmaxf(tmax, __shfl_xor_sync(0xffffffffu, tmax, 1));
            tmax = fmaxf(tmax, __shfl_xor_sync(0xffffffffu, tmax, 2));
            tmax = fmaxf(tmax, __shfl_xor_sync(0xffffffffu, tmax, 4));
            tmax = fmaxf(tmax, __shfl_xor_sync(0xffffffffu, tmax, 8));
            float m_new = fmaxf(m_i[r], tmax);
            float scale = __expf(m_i[r] - m_new);
            float p0 = __expf(s0 - m_new);
            float p1 = __expf(s1 - m_new);
            float p2 = __expf(s2 - m_new);
            float p3 = __expf(s3 - m_new);
            int row = ri*4 + r;
            Ps[(jc*4+0)*PS_W + row] = p0;
            Ps[(jc*4+1)*PS_W + row] = p1;
            Ps[(jc*4+2)*PS_W + row] = p2;
            Ps[(jc*4+3)*PS_W + row] = p3;
            float psum = (p0+p1) + (p2+p3);
            psum += __shfl_xor_sync(0xffffffffu, psum, 1);
            psum += __shfl_xor_sync(0xffffffffu, psum, 2);
            psum += __shfl_xor_sync(0xffffffffu, psum, 4);
            psum += __shfl_xor_sync(0xffffffffu, psum, 8);
            l_i[r] = l_i[r]*scale + psum;
            m_i[r] = m_new;
            if (jc == 0) scs[row] = scale;
        }
        __syncthreads();

        // ---- PV stage: 8 rows x 8 cols per thread ----
        #pragma unroll
        for (int r = 0; r < 8; r++) {
            float sv = scs[rg*8 + r];
            unsigned long long s2;
            asm("mov.b64 %0, {%1,%1};" : "=l"(s2) : "f"(sv));
            #pragma unroll
            for (int k = 0; k < 4; k++)
                asm("mul.rn.f32x2 %0, %0, %1;" : "+l"(acc[r*4+k]) : "l"(s2));
        }
        #pragma unroll 2
        for (int j = 0; j < 64; j++) {
            float4 pa = *(const float4*)(Ps + j*PS_W + rg*8);
            float4 pb = *(const float4*)(Ps + j*PS_W + rg*8 + 4);
            float4 va = *(const float4*)(Vs + j*VS_W + cg*4);
            float4 vb = *(const float4*)(Vs + j*VS_W + 128 + cg*4);
            unsigned long long v0,v1,v2,v3;
            asm("mov.b64 %0, {%1,%2};" : "=l"(v0) : "f"(va.x), "f"(va.y));
            asm("mov.b64 %0, {%1,%2};" : "=l"(v1) : "f"(va.z), "f"(va.w));
            asm("mov.b64 %0, {%1,%2};" : "=l"(v2) : "f"(vb.x), "f"(vb.y));
            asm("mov.b64 %0, {%1,%2};" : "=l"(v3) : "f"(vb.z), "f"(vb.w));
            const float* pp = (const float*)&pa;
            const float* pq = (const float*)&pb;
            #pragma unroll
            for (int r = 0; r < 4; r++) {
                unsigned long long p2;
                asm("mov.b64 %0, {%1,%1};" : "=l"(p2) : "f"(pp[r]));
                asm("fma.rn.f32x2 %0, %1, %2, %0;" : "+l"(acc[r*4+0]) : "l"(v0), "l"(p2));
                asm("fma.rn.f32x2 %0, %1, %2, %0;" : "+l"(acc[r*4+1]) : "l"(v1), "l"(p2));
                asm("fma.rn.f32x2 %0, %1, %2, %0;" : "+l"(acc[r*4+2]) : "l"(v2), "l"(p2));
                asm("fma.rn.f32x2 %0, %1, %2, %0;" : "+l"(acc[r*4+3]) : "l"(v3), "l"(p2));
            }
            #pragma unroll
            for (int r = 4; r < 8; r++) {
                unsigned long long p2;
                asm("mov.b64 %0, {%1,%1};" : "=l"(p2) : "f"(pq[r-4]));
                asm("fma.rn.f32x2 %0, %1, %2, %0;" : "+l"(acc[r*4+0]) : "l"(v0), "l"(p2));
                asm("fma.rn.f32x2 %0, %1, %2, %0;" : "+l"(acc[r*4+1]) : "l"(v1), "l"(p2));
                asm("fma.rn.f32x2 %0, %1, %2, %0;" : "+l"(acc[r*4+2]) : "l"(v2), "l"(p2));
                asm("fma.rn.f32x2 %0, %1, %2, %0;" : "+l"(acc[r*4+3]) : "l"(v3), "l"(p2));
            }
        }
    }

    // store row sums
    if (jc == 0) {
        #pragma unroll
        for (int r = 0; r < 4; r++) ls[ri*4 + r] = l_i[r];
    }
    __syncthreads();                    // all PV reads of Vs done

    // normalize + stage O into smem (reuse Vs, stride VS_W)
    float* Os = Vs;
    #pragma unroll
    for (int r = 0; r < 8; r++) {
        int row = rg*8 + r;
        float inv = 1.0f / ls[row];
        unsigned long long inv2;
        asm("mov.b64 %0, {%1,%1};" : "=l"(inv2) : "f"(inv));
        unsigned long long o0, o1, o2, o3;
        asm("mul.rn.f32x2 %0, %1, %2;" : "=l"(o0) : "l"(acc[r*4+0]), "l"(inv2));
        asm("mul.rn.f32x2 %0, %1, %2;" : "=l"(o1) : "l"(acc[r*4+1]), "l"(inv2));
        asm("mul.rn.f32x2 %0, %1, %2;" : "=l"(o2) : "l"(acc[r*4+2]), "l"(inv2));
        asm("mul.rn.f32x2 %0, %1, %2;" : "=l"(o3) : "l"(acc[r*4+3]), "l"(inv2));
        ulonglong2* da = (ulonglong2*)(Os + row*VS_W + cg*4);
        ulonglong2* db = (ulonglong2*)(Os + row*VS_W + 128 + cg*4);
        *da = make_ulonglong2(o0, o1);
        *db = make_ulonglong2(o2, o3);
    }
    __syncthreads();

    // coalesced output + residual: out[b][c][i0+n] = x + Os[n][c]
    const int chi = t >> 6;
    const int n   = t & 63;
    const float* xb = x   + (size_t)b*Cc*Nn;
    float*       ob = out + (size_t)b*Cc*Nn;
    #pragma unroll 4
    for (int ccc = 0; ccc < 64; ccc++) {
        int c = chi*64 + ccc;
        size_t g = (size_t)c*Nn + i0 + n;
        ob[g] = xb[g] + Os[n*VS_W + c];
    }
}

// ---------------------------------------------------------------------------
extern "C" void kernel_launch(void* const* d_in, const int* in_sizes, int n_in,
                              void* d_out, int out_size)
{
    const float* x  = (const float*)d_in[0];
    const float* Wq = (const float*)d_in[1];
    const float* bq = (const float*)d_in[2];
    const float* Wk = (const float*)d_in[3];
    const float* bk = (const float*)d_in[4];
    const float* Wv = (const float*)d_in[5];
    const float* bv = (const float*)d_in[6];
    float* out = (float*)d_out;

    const int smem_bytes = SMEM_FLOATS * 4;
    cudaFuncSetAttribute(attn_kernel, cudaFuncAttributeMaxDynamicSharedMemorySize,
                         smem_bytes);

    proj_kernel<<<dim3(Nn/128, 320/64, Bc), 256>>>(x, Wq, bq, Wk, bk, Wv, bv);
    attn_kernel<<<dim3(Nn/64, Bc), 256, smem_bytes>>>(x, out);
}